// round 7
// baseline (speedup 1.0000x reference)
#include <cuda_runtime.h>

#define NQ 65536   // B*H*W queries
#define DD 128     // feature dim
#define KK 1024    // codebook size

// Single self-contained kernel. CTA = 256 threads, 64 queries; 64 tiles of 16
// codes. Thread (tx=tid&3, ty=tid>>2): 1 query x 4 codes {tx+4*cj}.
// Smem floats: As[64*132] + Bs[16*132] + c2s[1024] = 11584 (46336 B < 48K).
#define AS_STRIDE 132
#define AS_FLOATS (64 * AS_STRIDE)
#define BS_FLOATS (16 * AS_STRIDE)
#define SMEM_FLOATS (AS_FLOATS + BS_FLOATS + KK)

__global__ __launch_bounds__(256) void vq_all_kernel(
    const float* __restrict__ z, const float* __restrict__ cb,
    float* __restrict__ out) {
    extern __shared__ float sm[];
    float* As  = sm;                          // [64][132] query-major z tile
    float* Bs  = sm + AS_FLOATS;              // [16][132] code-major cb tile
    float* c2s = sm + AS_FLOATS + BS_FLOATS;  // [1024] code norms

    const int tid = threadIdx.x;
    const int tx  = tid & 3;               // code sub-group
    const int ty  = tid >> 2;              // query 0..63
    const int q0  = blockIdx.x * 64;

    // ---- Load As[q][k] (stride 132). Coalesced LDG.128 -> conflict-free STS.
#pragma unroll
    for (int i = 0; i < 8; ++i) {
        const int idx = tid + i * 256;
        const int row = idx >> 5, col4 = idx & 31;
        const float4 v =
            *reinterpret_cast<const float4*>(&z[(q0 + row) * DD + col4 * 4]);
        *reinterpret_cast<float4*>(&As[row * AS_STRIDE + col4 * 4]) = v;
    }

    // ---- z2 estimate for this thread's query (split over 4 tx lanes; only
    //      used to derive the reference's quantization grid = ulp(z2+score)).
    float zs = 0.f;
#pragma unroll
    for (int k4 = 0; k4 < 8; ++k4) {
        const float4 v = *reinterpret_cast<const float4*>(
            &z[(q0 + ty) * DD + (tx * 8 + k4) * 4]);
        zs = fmaf(v.x, v.x, zs); zs = fmaf(v.y, v.y, zs);
        zs = fmaf(v.z, v.z, zs); zs = fmaf(v.w, v.w, zs);
    }
    zs += __shfl_xor_sync(0xffffffffu, zs, 1);
    zs += __shfl_xor_sync(0xffffffffu, zs, 2);   // all 4 lanes: ~||z_q||^2

    // ---- c2s: cooperative ||c||^2 for all 1024 codes.
#pragma unroll
    for (int j = 0; j < 4; ++j) {
        const int c = tid + j * 256;
        float s = 0.f;
#pragma unroll 8
        for (int k4 = 0; k4 < 32; ++k4) {
            const float4 v =
                *reinterpret_cast<const float4*>(&cb[c * DD + k4 * 4]);
            s = fmaf(v.x, v.x, s); s = fmaf(v.y, v.y, s);
            s = fmaf(v.z, v.z, s); s = fmaf(v.w, v.w, s);
        }
        c2s[c] = s;
    }

    const float4* As4 = reinterpret_cast<const float4*>(As);
    const float4* Bs4 = reinterpret_cast<const float4*>(Bs);

    // Top-2 tracking (value, index), first-occurrence on exact ties.
    float v0 = 3.4e38f, v1 = 3.4e38f;
    int i0 = 0, i1 = 0;

    for (int t = 0; t < 64; ++t) {
        __syncthreads();  // covers As/c2s on t=0; prior-tile readers after
#pragma unroll
        for (int i = 0; i < 2; ++i) {
            const int idx = tid + i * 256;
            const int row = idx >> 5, col4 = idx & 31;
            const float4 v = *reinterpret_cast<const float4*>(
                &cb[(t * 16 + row) * DD + col4 * 4]);
            *reinterpret_cast<float4*>(&Bs[row * AS_STRIDE + col4 * 4]) = v;
        }
        __syncthreads();

        float acc0 = 0.f, acc1 = 0.f, acc2 = 0.f, acc3 = 0.f;
#pragma unroll 8
        for (int k4 = 0; k4 < 32; ++k4) {
            const float4 a = As4[ty * 33 + k4];
            const float4 b0 = Bs4[(tx + 0) * 33 + k4];
            const float4 b1 = Bs4[(tx + 4) * 33 + k4];
            const float4 b2 = Bs4[(tx + 8) * 33 + k4];
            const float4 b3 = Bs4[(tx + 12) * 33 + k4];
            acc0 = fmaf(a.x, b0.x, acc0); acc0 = fmaf(a.y, b0.y, acc0);
            acc0 = fmaf(a.z, b0.z, acc0); acc0 = fmaf(a.w, b0.w, acc0);
            acc1 = fmaf(a.x, b1.x, acc1); acc1 = fmaf(a.y, b1.y, acc1);
            acc1 = fmaf(a.z, b1.z, acc1); acc1 = fmaf(a.w, b1.w, acc1);
            acc2 = fmaf(a.x, b2.x, acc2); acc2 = fmaf(a.y, b2.y, acc2);
            acc2 = fmaf(a.z, b2.z, acc2); acc2 = fmaf(a.w, b2.w, acc2);
            acc3 = fmaf(a.x, b3.x, acc3); acc3 = fmaf(a.y, b3.y, acc3);
            acc3 = fmaf(a.z, b3.z, acc3); acc3 = fmaf(a.w, b3.w, acc3);
        }

        const int cb0 = t * 16 + tx;
        const float m0 = fmaf(-2.f, acc0, c2s[cb0]);
        const float m1 = fmaf(-2.f, acc1, c2s[cb0 + 4]);
        const float m2 = fmaf(-2.f, acc2, c2s[cb0 + 8]);
        const float m3 = fmaf(-2.f, acc3, c2s[cb0 + 12]);

        // Ascending-index candidates; strict < keeps first occurrence.
#define TOP2_UPD(mv, ci)                                        \
        if ((mv) < v0)      { v1 = v0; i1 = i0; v0 = (mv); i0 = (ci); } \
        else if ((mv) < v1) { v1 = (mv); i1 = (ci); }
        TOP2_UPD(m0, cb0);
        TOP2_UPD(m1, cb0 + 4);
        TOP2_UPD(m2, cb0 + 8);
        TOP2_UPD(m3, cb0 + 12);
#undef TOP2_UPD
    }

    // ---- Merge top-2 across the 4 tx lanes (xor 1,2 stays in-group).
#pragma unroll
    for (int off = 1; off < 4; off <<= 1) {
        const float w0 = __shfl_xor_sync(0xffffffffu, v0, off);
        const int   j0 = __shfl_xor_sync(0xffffffffu, i0, off);
        const float w1 = __shfl_xor_sync(0xffffffffu, v1, off);
        const int   j1 = __shfl_xor_sync(0xffffffffu, i1, off);
        if (w0 < v0 || (w0 == v0 && j0 < i0)) {
            v1 = v0; i1 = i0; v0 = w0; i0 = j0;
        } else if (w0 < v1 || (w0 == v1 && j0 < i1)) {
            v1 = w0; i1 = j0;
        }
        if (w1 < v0 || (w1 == v0 && j1 < i0)) {
            v1 = v0; i1 = i0; v0 = w1; i0 = j1;
        } else if (w1 < v1 || (w1 == v1 && j1 < i1)) {
            v1 = w1; i1 = j1;
        }
    }

    if (tx == 0) {
        // Reference grid: its dist2 = (z2 - 2*dot) + c2 lives near z2 (~128),
        // quantized at ulp(z2+score). If top-2 fall within one grid step and
        // the runner-up has the smaller index, the reference's quantized tie
        // + argmin-first-occurrence picks the runner-up.
        const float sfull = zs + v0;                     // ~reference magnitude
        const int ebits = (__float_as_int(sfull) >> 23) & 0xff;
        const float u = __int_as_float((ebits - 23) << 23);   // ulp(sfull)
        int win = i0;
        if (v1 - v0 <= u && i1 < i0) win = i1;
        out[q0 + ty] = (float)win;
    }
}

extern "C" void kernel_launch(void* const* d_in, const int* in_sizes, int n_in,
                              void* d_out, int out_size) {
    const float* z  = (const float*)d_in[0];
    const float* cb = (const float*)d_in[1];
    if (n_in >= 2 && in_sizes[0] == KK * DD) {  // defensive order check
        cb = (const float*)d_in[0];
        z  = (const float*)d_in[1];
    }
    vq_all_kernel<<<NQ / 64, 256, SMEM_FLOATS * sizeof(float)>>>(
        z, cb, (float*)d_out);
}

// round 8
// speedup vs baseline: 2.3439x; 2.3439x over previous
#include <cuda_runtime.h>

#define NQ 65536   // queries
#define DD 128     // dims
#define KK 1024    // codes
#define ASTR 132   // padded smem row stride (floats), 16B-aligned rows

// Thread layout: 256 threads = 16 tx * 16 ty.
// Thread tile: 8 queries {ty*4+i, 64+ty*4+i} x 8 codes {tx*4+j, 64+tx*4+j}.
// CTA: 128 queries x all 1024 codes (8 blocks of 128), dims staged 16 at a time.

__device__ __forceinline__ unsigned long long dup_f32x2(float a) {
    unsigned long long r;
    asm("mov.b64 %0, {%1, %1};" : "=l"(r) : "f"(a));
    return r;
}
__device__ __forceinline__ void fma2(unsigned long long& d,
                                     unsigned long long a,
                                     unsigned long long b) {
    asm("fma.rn.f32x2 %0, %1, %2, %0;" : "+l"(d) : "l"(a), "l"(b));
}
__device__ __forceinline__ void unpack2(unsigned long long v, float& lo,
                                        float& hi) {
    asm("mov.b64 {%0, %1}, %2;" : "=f"(lo), "=f"(hi) : "l"(v));
}

__global__ __launch_bounds__(256) void vq_kernel(
    const float* __restrict__ z, const float* __restrict__ cb,
    float* __restrict__ out) {
    __shared__ float As[16 * ASTR];   // [k][q] staged query tile
    __shared__ float Bs[16 * ASTR];   // [k][c] staged code tile
    __shared__ float c2s[KK];
    __shared__ float z2s[128];

    const int tid = threadIdx.x;
    const int tx = tid & 15;
    const int ty = tid >> 4;
    const int q0 = blockIdx.x * 128;

    // ---- c2s: ||c||^2 for all 1024 codes (4 per thread)
#pragma unroll
    for (int j = 0; j < 4; ++j) {
        const int c = tid + j * 256;
        float s = 0.f;
#pragma unroll 8
        for (int k4 = 0; k4 < 32; ++k4) {
            const float4 v =
                *reinterpret_cast<const float4*>(&cb[c * DD + k4 * 4]);
            s = fmaf(v.x, v.x, s); s = fmaf(v.y, v.y, s);
            s = fmaf(v.z, v.z, s); s = fmaf(v.w, v.w, s);
        }
        c2s[c] = s;
    }
    // ---- z2s: ||z_q||^2 for this CTA's 128 queries (ulp-grid tie-break only)
    if (tid < 128) {
        float s = 0.f;
#pragma unroll 8
        for (int k4 = 0; k4 < 32; ++k4) {
            const float4 v = *reinterpret_cast<const float4*>(
                &z[(q0 + tid) * DD + k4 * 4]);
            s = fmaf(v.x, v.x, s); s = fmaf(v.y, v.y, s);
            s = fmaf(v.z, v.z, s); s = fmaf(v.w, v.w, s);
        }
        z2s[tid] = s;
    }

    // Top-2 per query (first-occurrence semantics)
    float v0[8], v1[8];
    int i0[8], i1[8];
#pragma unroll
    for (int q = 0; q < 8; ++q) {
        v0[q] = 3.4e38f; v1[q] = 3.4e38f; i0[q] = 0; i1[q] = 0;
    }

    for (int cblk = 0; cblk < 8; ++cblk) {
        unsigned long long acc[8][4];
#pragma unroll
        for (int q = 0; q < 8; ++q)
#pragma unroll
            for (int p = 0; p < 4; ++p) acc[q][p] = 0ull;  // (0.f, 0.f)

        for (int kc = 0; kc < 8; ++kc) {
            __syncthreads();  // prior readers done (also covers c2s/z2s @first)
            // Stage As/Bs: 128 rows x 16 dims each, transposed to [k][row].
#pragma unroll
            for (int i = 0; i < 2; ++i) {
                const int idx = tid + i * 256;       // 0..511
                const int row = idx >> 2, d4 = idx & 3;
                const float4 va = *reinterpret_cast<const float4*>(
                    &z[(q0 + row) * DD + kc * 16 + d4 * 4]);
                As[(d4 * 4 + 0) * ASTR + row] = va.x;
                As[(d4 * 4 + 1) * ASTR + row] = va.y;
                As[(d4 * 4 + 2) * ASTR + row] = va.z;
                As[(d4 * 4 + 3) * ASTR + row] = va.w;
                const float4 vb = *reinterpret_cast<const float4*>(
                    &cb[(cblk * 128 + row) * DD + kc * 16 + d4 * 4]);
                Bs[(d4 * 4 + 0) * ASTR + row] = vb.x;
                Bs[(d4 * 4 + 1) * ASTR + row] = vb.y;
                Bs[(d4 * 4 + 2) * ASTR + row] = vb.z;
                Bs[(d4 * 4 + 3) * ASTR + row] = vb.w;
            }
            __syncthreads();

#pragma unroll 4
            for (int k = 0; k < 16; ++k) {
                const float4 a0 =
                    *reinterpret_cast<const float4*>(&As[k * ASTR + ty * 4]);
                const float4 a1 = *reinterpret_cast<const float4*>(
                    &As[k * ASTR + 64 + ty * 4]);
                const double2 b0 =
                    *reinterpret_cast<const double2*>(&Bs[k * ASTR + tx * 4]);
                const double2 b1 = *reinterpret_cast<const double2*>(
                    &Bs[k * ASTR + 64 + tx * 4]);
                const unsigned long long bb[4] = {
                    __double_as_longlong(b0.x), __double_as_longlong(b0.y),
                    __double_as_longlong(b1.x), __double_as_longlong(b1.y)};
                const unsigned long long aa[8] = {
                    dup_f32x2(a0.x), dup_f32x2(a0.y), dup_f32x2(a0.z),
                    dup_f32x2(a0.w), dup_f32x2(a1.x), dup_f32x2(a1.y),
                    dup_f32x2(a1.z), dup_f32x2(a1.w)};
#pragma unroll
                for (int q = 0; q < 8; ++q)
#pragma unroll
                    for (int p = 0; p < 4; ++p) fma2(acc[q][p], aa[q], bb[p]);
            }
        }

        // ---- scores for this code block; ascending code order per query
        const int cbase = cblk * 128;
#pragma unroll
        for (int q = 0; q < 8; ++q) {
#pragma unroll
            for (int p = 0; p < 4; ++p) {
                const int cc =
                    cbase + ((p < 2) ? (tx * 4 + p * 2) : (64 + tx * 4 + (p - 2) * 2));
                float dlo, dhi;
                unpack2(acc[q][p], dlo, dhi);
                const float mlo = fmaf(-2.f, dlo, c2s[cc]);
                const float mhi = fmaf(-2.f, dhi, c2s[cc + 1]);
                if (mlo < v0[q]) {
                    v1[q] = v0[q]; i1[q] = i0[q]; v0[q] = mlo; i0[q] = cc;
                } else if (mlo < v1[q]) { v1[q] = mlo; i1[q] = cc; }
                if (mhi < v0[q]) {
                    v1[q] = v0[q]; i1[q] = i0[q]; v0[q] = mhi; i0[q] = cc + 1;
                } else if (mhi < v1[q]) { v1[q] = mhi; i1[q] = cc + 1; }
            }
        }
    }

    // ---- merge top-2 across the 16 tx lanes (xor 1..8 stays in 16-lane half)
#pragma unroll
    for (int off = 1; off < 16; off <<= 1) {
#pragma unroll
        for (int q = 0; q < 8; ++q) {
            const float w0 = __shfl_xor_sync(0xffffffffu, v0[q], off);
            const int j0 = __shfl_xor_sync(0xffffffffu, i0[q], off);
            const float w1 = __shfl_xor_sync(0xffffffffu, v1[q], off);
            const int j1 = __shfl_xor_sync(0xffffffffu, i1[q], off);
            if (w0 < v0[q] || (w0 == v0[q] && j0 < i0[q])) {
                v1[q] = v0[q]; i1[q] = i0[q]; v0[q] = w0; i0[q] = j0;
            } else if (w0 < v1[q] || (w0 == v1[q] && j0 < i1[q])) {
                v1[q] = w0; i1[q] = j0;
            }
            if (w1 < v0[q] || (w1 == v0[q] && j1 < i0[q])) {
                v1[q] = v0[q]; i1[q] = i0[q]; v0[q] = w1; i0[q] = j1;
            } else if (w1 < v1[q] || (w1 == v1[q] && j1 < i1[q])) {
                v1[q] = w1; i1[q] = j1;
            }
        }
    }

    if (tx == 0) {
#pragma unroll
        for (int q = 0; q < 8; ++q) {
            const int lq = (q < 4) ? (ty * 4 + q) : (64 + ty * 4 + (q - 4));
            // Reference grid: dist2 = (z2 - 2*dot) + c2 quantized at ulp(z2+s).
            const float sfull = z2s[lq] + v0[q];
            const int ebits = (__float_as_int(sfull) >> 23) & 0xff;
            const float u = __int_as_float((ebits - 23) << 23);  // ulp(sfull)
            int win = i0[q];
            if (v1[q] - v0[q] <= u && i1[q] < i0[q]) win = i1[q];
            out[q0 + lq] = (float)win;
        }
    }
}

extern "C" void kernel_launch(void* const* d_in, const int* in_sizes, int n_in,
                              void* d_out, int out_size) {
    const float* z  = (const float*)d_in[0];
    const float* cb = (const float*)d_in[1];
    if (n_in >= 2 && in_sizes[0] == KK * DD) {  // defensive order check
        cb = (const float*)d_in[0];
        z  = (const float*)d_in[1];
    }
    vq_kernel<<<NQ / 128, 256>>>(z, cb, (float*)d_out);
}